// round 7
// baseline (speedup 1.0000x reference)
#include <cuda_runtime.h>
#include <math.h>
#include <stdint.h>
#include <float.h>

#define MAXB  128
#define CAP   4096
#define NBINS 2048     // coarse subsample bins
#define FB    4096     // fine ranking bins
#define NT    1024

// Global scratch: only used by the (statistically never-taken) fallback path.
__device__ float g_cval[MAXB * CAP];
__device__ int   g_cidx[MAXB * CAP];

__device__ __forceinline__ int bin_of(float x) {
    int b = (int)floorf((x + 32.0f) * 32.0f);   // width 1/32 over [-32, 32]
    b = b < 0 ? 0 : b;
    return b > (NBINS - 1) ? (NBINS - 1) : b;
}

__device__ __forceinline__ float warp_red_sum(float v) {
    #pragma unroll
    for (int o = 16; o; o >>= 1) v += __shfl_xor_sync(0xffffffffu, v, o);
    return v;
}
__device__ __forceinline__ float warp_red_max(float v) {
    #pragma unroll
    for (int o = 16; o; o >>= 1) v = fmaxf(v, __shfl_xor_sync(0xffffffffu, v, o));
    return v;
}

__device__ __forceinline__ float block_incl_scan(float v, float* wsum, int lane, int wid) {
    #pragma unroll
    for (int off = 1; off < 32; off <<= 1) {
        float n = __shfl_up_sync(0xffffffffu, v, off);
        if (lane >= off) v += n;
    }
    __syncthreads();
    if (lane == 31) wsum[wid] = v;
    __syncthreads();
    if (wid == 0) {
        float w = wsum[lane];
        #pragma unroll
        for (int off = 1; off < 32; off <<= 1) {
            float n = __shfl_up_sync(0xffffffffu, w, off);
            if (lane >= off) w += n;
        }
        wsum[lane] = w;
    }
    __syncthreads();
    return v + (wid ? wsum[wid - 1] : 0.f);
}

__device__ __forceinline__ int block_incl_scan_int(int v, int* wsum, int lane, int wid) {
    #pragma unroll
    for (int off = 1; off < 32; off <<= 1) {
        int n = __shfl_up_sync(0xffffffffu, v, off);
        if (lane >= off) v += n;
    }
    __syncthreads();
    if (lane == 31) wsum[wid] = v;
    __syncthreads();
    if (wid == 0) {
        int w = wsum[lane];
        #pragma unroll
        for (int off = 1; off < 32; off <<= 1) {
            int n = __shfl_up_sync(0xffffffffu, w, off);
            if (lane >= off) w += n;
        }
        wsum[lane] = w;
    }
    __syncthreads();
    return v + (wid ? wsum[wid - 1] : 0);
}

// order-preserving float <-> u32
__device__ __forceinline__ unsigned fmap(float x) {
    unsigned fb = __float_as_uint(x);
    return (fb & 0x80000000u) ? ~fb : (fb | 0x80000000u);
}
__device__ __forceinline__ float funmap(unsigned mu) {
    unsigned fb = (mu & 0x80000000u) ? (mu & 0x7FFFFFFFu) : ~mu;
    return __uint_as_float(fb);
}

// descending sort order: larger key first, then smaller idx first
__device__ __forceinline__ bool kv_gt(unsigned k1, unsigned p1, unsigned k2, unsigned p2) {
    return (k1 > k2) || (k1 == k2 && p1 < p2);
}
__device__ __forceinline__ void ce_sh(unsigned* kv, unsigned* pv, int i, int j, int K) {
    unsigned k1 = kv[i], p1 = pv[i], k2 = kv[i + j], p2 = pv[i + j];
    bool sw = ((i & K) == 0) ? kv_gt(k2, p2, k1, p1) : kv_gt(k1, p1, k2, p2);
    if (sw) { kv[i] = k2; pv[i] = p2; kv[i + j] = k1; pv[i + j] = p1; }
}

// ============================ ONE fused kernel ============================
__global__ void __launch_bounds__(NT) k_fused(const float* __restrict__ logits,
                                              const float* __restrict__ temps,
                                              const int*   __restrict__ top_ks,
                                              const float* __restrict__ top_ps,
                                              const float* __restrict__ min_ps,
                                              const float* __restrict__ u,
                                              float* __restrict__ out,
                                              int V, int B, int tokens_first)
{
    const int row = blockIdx.x;
    const int tid = threadIdx.x;
    const int lane = tid & 31, wid = tid >> 5;

    // Arena layout (u32 words), 40 KB:
    //  [0..2047]     hist (phase B) -> skv (rank keys) ; fallback fkv[0..4095]
    //  [2048..4095]  cval (candidate values)
    //  [4096..6143]  cidx (candidate indices)        ; fallback fkp[4096..8191]
    //  [6144..8191]  packed u16x2 fine bins (4096 bins in 2048 words)
    //  [8192..10239] skp (rank payloads)
    __shared__ unsigned arena[10240];
    __shared__ float wred[32];
    __shared__ int   iwsum[32];
    __shared__ float s_S, s_shift, s_mx;
    __shared__ int   s_bt, s_cnt, s_bad;
    __shared__ float sh_p0, sh_tot;

    int*      hist  = (int*)arena;
    float*    cval  = (float*)(arena + 2048);
    int*      cidx  = (int*)(arena + 4096);
    unsigned* binsw = arena + 6144;
    unsigned* skvA  = arena;
    unsigned* skpA  = arena + 8192;

    float* probs_out = tokens_first ? (out + B) : out;
    float* prow = probs_out + (size_t)row * V;
    const float* lrow = logits + (size_t)row * V;
    const float invT = 1.0f / temps[row];
    const int need = V < 1024 ? V : 1024;
    const int V4 = V >> 2;
    const float4* l4 = (const float4*)lrow;

    // ---- Phase 0: zero this row's output (streaming stores drain under compute) ----
    if ((V & 3) == 0 && ((B & 3) == 0 || !tokens_first)) {
        float4* p4 = (float4*)prow;
        const float4 z4 = make_float4(0.f, 0.f, 0.f, 0.f);
        for (int i = tid; i < V4; i += NT) __stcs(p4 + i, z4);
    } else {
        for (int i = tid; i < V; i += NT) __stcs(prow + i, 0.f);
    }
    if (tid == 0) { s_cnt = 0; s_bad = 0; s_bt = 1024; }

    // ---- Phase 1: 16k-point coalesced subsample histogram -> threshold ----
    if (V > CAP) {
        for (int t = tid; t < NBINS; t += NT) hist[t] = 0;
        __syncthreads();
        int step4 = V4 / 4096; if (step4 < 1) step4 = 1;
        int ns4 = V4 / step4; if (ns4 > 4096) ns4 = 4096;
        int subN = ns4 * 4;
        for (int j = tid; j < ns4; j += NT) {
            float4 v = l4[(size_t)j * step4];
            if (v.x > 2.0f) atomicAdd(&hist[bin_of(v.x)], 1);
            if (v.y > 2.0f) atomicAdd(&hist[bin_of(v.y)], 1);
            if (v.z > 2.0f) atomicAdd(&hist[bin_of(v.z)], 1);
            if (v.w > 2.0f) atomicAdd(&hist[bin_of(v.w)], 1);
        }
        __syncthreads();
        // target expected true count ~1.55*need (>=4 sigma inside [1024, 2048])
        int tgt = (int)(((long long)need * 31LL * subN) / (20LL * (long long)V));
        if (tgt < 1) tgt = 1;
        int b = 2047 - tid;
        int v = (tid < 960) ? hist[b] : 0;
        int sfx = block_incl_scan_int(v, iwsum, lane, wid);
        if (tid < 960 && sfx >= tgt && sfx - v < tgt) s_bt = b;
        __syncthreads();
    }
    const float xthr = (V > CAP) ? ((float)s_bt * 0.03125f - 32.0f) : -FLT_MAX;
    __syncthreads();   // hist dead; s_cnt visible

    // ---- Phase 2: single full pass: max + sum(__expf) + warp-aggregated gather ----
    float s = 0.f, s2 = 0.f, mx = -FLT_MAX;
    const int iters = (V4 + NT - 1) / NT;
    for (int it = 0; it < iters; it++) {
        int i = tid + it * NT;
        bool in = i < V4;
        float4 v = in ? l4[i] : make_float4(-FLT_MAX, -FLT_MAX, -FLT_MAX, -FLT_MAX);
        mx = fmaxf(mx, fmaxf(fmaxf(v.x, v.y), fmaxf(v.z, v.w)));
        s  += __expf(v.x * invT) + __expf(v.y * invT);     // exp(-inf)=0 for padding
        s2 += __expf(v.z * invT) + __expf(v.w * invT);
        #pragma unroll
        for (int c = 0; c < 4; c++) {
            float x = (c == 0) ? v.x : (c == 1) ? v.y : (c == 2) ? v.z : v.w;
            bool pred = (x >= xthr);                        // padding never passes
            unsigned m = __ballot_sync(0xffffffffu, pred);
            if (m) {
                int leader = __ffs(m) - 1;
                int wcnt = __popc(m);
                int base = 0;
                if (lane == leader) base = atomicAdd(&s_cnt, wcnt);
                base = __shfl_sync(0xffffffffu, base, leader);
                if (pred) {
                    int pos = base + __popc(m & ((1u << lane) - 1u));
                    if (pos < 2048) { cval[pos] = x; cidx[pos] = (i << 2) + c; }
                }
            }
        }
    }
    s += s2;
    for (int t = (V4 << 2) + tid; t < V; t += NT) {         // tail (V%4)
        float x = lrow[t];
        mx = fmaxf(mx, x);
        s += __expf(x * invT);
        if (x >= xthr) {
            int pos = atomicAdd(&s_cnt, 1);
            if (pos < 2048) { cval[pos] = x; cidx[pos] = t; }
        }
    }

    // ---- Phase 3: reductions ----
    s = warp_red_sum(s);
    if (lane == 0) wred[wid] = s;
    __syncthreads();
    if (wid == 0) { float t = warp_red_sum(wred[lane]); if (lane == 0) s_S = t; }
    __syncthreads();
    mx = warp_red_max(mx);
    if (lane == 0) wred[wid] = mx;
    __syncthreads();
    if (wid == 0) {
        float t = warp_red_max(wred[lane]);
        if (lane == 0) {
            s_mx = t;
            float mxT = t * invT;
            s_shift = (mxT > 80.f || !isfinite(s_S)) ? mxT : 0.f;
        }
    }
    __syncthreads();
    const float shift = s_shift;
    if (shift != 0.f) {        // rare overflow-safe recompute (precise path)
        s = 0.f;
        for (int t = tid; t < V; t += NT) s += expf(lrow[t] * invT - shift);
        s = warp_red_sum(s);
        if (lane == 0) wred[wid] = s;
        __syncthreads();
        if (wid == 0) { float t = warp_red_sum(wred[lane]); if (lane == 0) s_S = t; }
        __syncthreads();
    }

    int C = s_cnt;
    const float lo = xthr, hi = s_mx;
    const float range = hi - lo;
    bool ok = (V > CAP) && (C >= need) && (C <= 2048) && (range > 0.f) && isfinite(range);

    unsigned *pk = skvA, *pp = skpA;

    if (ok) {
        // ---- Phase 4: histogram ranking (4096 fine bins, packed u16 counters) ----
        const float scale = (float)FB / range;
        unsigned k0 = 0, k1 = 0; int i0 = 0, i1 = 0, b0 = 0, b1 = 0;
        float x0 = 0.f, x1 = 0.f;
        if (tid < C)        { x0 = cval[tid];        i0 = cidx[tid];        k0 = fmap(x0); }
        if (tid + 1024 < C) { x1 = cval[tid + 1024]; i1 = cidx[tid + 1024]; k1 = fmap(x1); }
        binsw[tid] = 0; binsw[tid + 1024] = 0;
        __syncthreads();
        if (tid < C) {
            b0 = (int)((x0 - lo) * scale); b0 = b0 < 0 ? 0 : (b0 > FB - 1 ? FB - 1 : b0);
            atomicAdd(&binsw[b0 >> 1], 1u << (16 * (b0 & 1)));
        }
        if (tid + 1024 < C) {
            b1 = (int)((x1 - lo) * scale); b1 = b1 < 0 ? 0 : (b1 > FB - 1 ? FB - 1 : b1);
            atomicAdd(&binsw[b1 >> 1], 1u << (16 * (b1 & 1)));
        }
        __syncthreads();
        // suffix scan in descending-bin order; thread t owns bins 4095-4t .. 4092-4t
        unsigned w1 = binsw[2047 - 2 * tid];
        unsigned w0 = binsw[2046 - 2 * tid];
        int cA = (int)(w1 >> 16), cB = (int)(w1 & 0xffffu);
        int cC = (int)(w0 >> 16), cD = (int)(w0 & 0xffffu);
        int tot4 = cA + cB + cC + cD;
        int base = block_incl_scan_int(tot4, iwsum, lane, wid) - tot4;
        binsw[2047 - 2 * tid] = ((unsigned)base << 16) | (unsigned)(base + cA);
        binsw[2046 - 2 * tid] = ((unsigned)(base + cA + cB) << 16) | (unsigned)(base + cA + cB + cC);
        __syncthreads();
        // scatter to rank slots
        if (tid < C) {
            unsigned old = atomicAdd(&binsw[b0 >> 1], 1u << (16 * (b0 & 1)));
            int sl = (int)((old >> (16 * (b0 & 1))) & 0xffffu);
            pk[sl] = k0; pp[sl] = (unsigned)i0;
        }
        if (tid + 1024 < C) {
            unsigned old = atomicAdd(&binsw[b1 >> 1], 1u << (16 * (b1 & 1)));
            int sl = (int)((old >> (16 * (b1 & 1))) & 0xffffu);
            pk[sl] = k1; pp[sl] = (unsigned)i1;
        }
        __syncthreads();
        // fixup within-bin order: insertion sort on contiguous same-bin runs
        #pragma unroll
        for (int e = 0; e < 2; e++) {
            int i = tid + e * 1024;
            if (i < C) {
                int bi = (int)((funmap(pk[i]) - lo) * scale); bi = bi < 0 ? 0 : (bi > FB - 1 ? FB - 1 : bi);
                int bp = -1;
                if (i > 0) {
                    bp = (int)((funmap(pk[i - 1]) - lo) * scale); bp = bp < 0 ? 0 : (bp > FB - 1 ? FB - 1 : bp);
                }
                if (bi != bp) {                       // run start
                    int L = 1;
                    while (i + L < C && L <= 16) {
                        int bn = (int)((funmap(pk[i + L]) - lo) * scale); bn = bn < 0 ? 0 : (bn > FB - 1 ? FB - 1 : bn);
                        if (bn != bi) break;
                        L++;
                    }
                    if (L > 16) { atomicExch(&s_bad, 1); }
                    else if (L > 1) {
                        unsigned lk[16], lp[16];
                        for (int t = 0; t < L; t++) { lk[t] = pk[i + t]; lp[t] = pp[i + t]; }
                        for (int a = 1; a < L; a++) {
                            unsigned ck = lk[a], cp = lp[a];
                            int b2 = a - 1;
                            while (b2 >= 0 && !kv_gt(lk[b2], lp[b2], ck, cp)) {
                                lk[b2 + 1] = lk[b2]; lp[b2 + 1] = lp[b2]; b2--;
                            }
                            lk[b2 + 1] = ck; lp[b2 + 1] = cp;
                        }
                        for (int t = 0; t < L; t++) { pk[i + t] = lk[t]; pp[i + t] = lp[t]; }
                    }
                }
            }
        }
        __syncthreads();
        if (s_bad) ok = false;
        __syncthreads();
    }

    if (!ok) {
        // ---- FALLBACK (~never): exact coarse hist -> global gather -> bitonic 4096 ----
        if (V <= CAP) {
            for (int t = tid; t < V; t += NT) { g_cval[row * CAP + t] = lrow[t]; g_cidx[row * CAP + t] = t; }
            if (tid == 0) s_cnt = V;
        } else {
            for (int t = tid; t < NBINS; t += NT) hist[t] = 0;
            __syncthreads();
            for (int t = tid; t < V; t += NT) atomicAdd(&hist[bin_of(lrow[t])], 1);
            __syncthreads();
            if (tid == 0) {
                int acc = 0, bt2 = 0;
                for (int b = NBINS - 1; b >= 0; b--) {
                    int na = acc + hist[b];
                    if (na >= need) { bt2 = (na <= CAP) ? b : (b + 1); break; }
                    acc = na;
                }
                s_bt = bt2; s_cnt = 0;
            }
            __syncthreads();
            const int bt2 = s_bt;
            for (int t = tid; t < V; t += NT) {
                float x = lrow[t];
                if (bin_of(x) >= bt2) {
                    int pos = atomicAdd(&s_cnt, 1);
                    if (pos < CAP) { g_cval[row * CAP + pos] = x; g_cidx[row * CAP + pos] = t; }
                }
            }
        }
        __syncthreads();
        C = s_cnt < CAP ? s_cnt : CAP;
        unsigned* fkv = arena;
        unsigned* fkp = arena + 4096;
        for (int i = tid; i < CAP; i += NT) {
            unsigned key = 0u, pay = 0xFFFFFFFFu;
            if (i < C) { key = fmap(g_cval[row * CAP + i]); pay = (unsigned)g_cidx[row * CAP + i]; }
            fkv[i] = key; fkp[i] = pay;
        }
        __syncthreads();
        for (int K = 2; K <= CAP; K <<= 1) {
            int j = K >> 1;
            for (; j >= 64; j >>= 1) {
                for (int c = tid; c < (CAP >> 1); c += NT) {
                    int i = ((c & ~(j - 1)) << 1) | (c & (j - 1));
                    ce_sh(fkv, fkp, i, j, K);
                }
                __syncthreads();
            }
            for (; j >= 1; j >>= 1) {
                for (int c = tid; c < (CAP >> 1); c += NT) {
                    int i = ((c & ~(j - 1)) << 1) | (c & (j - 1));
                    ce_sh(fkv, fkp, i, j, K);
                }
                __syncwarp();
            }
            __syncthreads();
        }
        pk = fkv; pp = fkp;
    }

    // ---- Phase 5: masks (reference order) + inverse-CDF sample + scatter ----
    const float S = s_S;
    float p = 0.f;
    int   myidx = 0;
    if (tid < C) {
        p = expf(funmap(pk[tid]) * invT - shift) / S;
        myidx = (int)pp[tid];
    }
    if (tid == 0) sh_p0 = p;

    float cumincl = block_incl_scan(p, wred, lane, wid);   // pre-mask cumsum

    const int   tk  = top_ks[row];
    const float tp  = top_ps[row];
    const float thr = sh_p0 * min_ps[row];
    float q = p;
    if (tid >= tk)        q = 0.f;   // top-k
    if (cumincl - q > tp) q = 0.f;   // top-p (cumsum computed pre-mask)
    if (q < thr)          q = 0.f;   // min-p

    float cq = block_incl_scan(q, wred, lane, wid);        // post-mask CDF numerator
    if (tid == NT - 1) sh_tot = cq;
    __syncthreads();
    const float tot  = sh_tot;
    const float uval = u[row];

    int rank = __syncthreads_count((cq / tot < uval) ? 1 : 0);
    if (rank > NT - 1) rank = NT - 1;
    if (rank > V - 1) rank = V - 1;

    if (tid == 0 && tokens_first) {
        out[row] = (float)(int)pp[rank];
    }
    if (q > 0.f) {
        prow[myidx] = q / tot;   // ordered after phase-0 zero stores by barriers
    }
}

extern "C" void kernel_launch(void* const* d_in, const int* in_sizes, int n_in,
                              void* d_out, int out_size)
{
    const float* logits = (const float*)d_in[0];
    const float* temps  = (const float*)d_in[1];
    const int*   topks  = (const int*)  d_in[2];
    const float* topps  = (const float*)d_in[3];
    const float* minps  = (const float*)d_in[4];
    const float* u      = (const float*)d_in[5];

    const int B = in_sizes[1];
    const int V = in_sizes[0] / B;
    float* out = (float*)d_out;
    int tokens_first = (out_size == B + B * V) ? 1 : 0;

    k_fused<<<B, NT>>>(logits, temps, topks, topps, minps, u, out, V, B, tokens_first);
}

// round 8
// speedup vs baseline: 1.0343x; 1.0343x over previous
#include <cuda_runtime.h>
#include <math.h>
#include <stdint.h>
#include <float.h>

#define MAXB  128
#define CAP   4096
#define NBINS 2048     // coarse subsample bins
#define FB    4096     // fine ranking bins
#define NT    1024

// Global scratch: only used by the (statistically never-taken) fallback path.
__device__ float g_cval[MAXB * CAP];
__device__ int   g_cidx[MAXB * CAP];

__device__ __forceinline__ int bin_of(float x) {
    int b = (int)floorf((x + 32.0f) * 32.0f);   // width 1/32 over [-32, 32]
    b = b < 0 ? 0 : b;
    return b > (NBINS - 1) ? (NBINS - 1) : b;
}

// exp(x*invT) on the FMA/ALU pipes (no MUFU): 2^(y) with y = x*invT*log2e.
// Degree-5 Taylor in f*ln2 on f in [-0.5, 0.5]; rel err ~2e-6 (S only needs 1e-4:
// it feeds ONLY the top-p boundary; it cancels exactly everywhere else).
__device__ __forceinline__ float fexp(float x, float k2) {
    float y = x * k2;
    y = fminf(fmaxf(y, -120.f), 120.f);
    float n = rintf(y);
    float f = y - n;
    float p = 1.33335581e-3f;
    p = fmaf(p, f, 9.61812911e-3f);
    p = fmaf(p, f, 5.55041087e-2f);
    p = fmaf(p, f, 2.40226507e-1f);
    p = fmaf(p, f, 6.93147181e-1f);
    p = fmaf(p, f, 1.0f);
    float e = __int_as_float(((int)n + 127) << 23);
    return p * e;
}

__device__ __forceinline__ float warp_red_sum(float v) {
    #pragma unroll
    for (int o = 16; o; o >>= 1) v += __shfl_xor_sync(0xffffffffu, v, o);
    return v;
}
__device__ __forceinline__ float warp_red_max(float v) {
    #pragma unroll
    for (int o = 16; o; o >>= 1) v = fmaxf(v, __shfl_xor_sync(0xffffffffu, v, o));
    return v;
}

__device__ __forceinline__ float block_incl_scan(float v, float* wsum, int lane, int wid) {
    #pragma unroll
    for (int off = 1; off < 32; off <<= 1) {
        float n = __shfl_up_sync(0xffffffffu, v, off);
        if (lane >= off) v += n;
    }
    __syncthreads();
    if (lane == 31) wsum[wid] = v;
    __syncthreads();
    if (wid == 0) {
        float w = wsum[lane];
        #pragma unroll
        for (int off = 1; off < 32; off <<= 1) {
            float n = __shfl_up_sync(0xffffffffu, w, off);
            if (lane >= off) w += n;
        }
        wsum[lane] = w;
    }
    __syncthreads();
    return v + (wid ? wsum[wid - 1] : 0.f);
}

__device__ __forceinline__ int block_incl_scan_int(int v, int* wsum, int lane, int wid) {
    #pragma unroll
    for (int off = 1; off < 32; off <<= 1) {
        int n = __shfl_up_sync(0xffffffffu, v, off);
        if (lane >= off) v += n;
    }
    __syncthreads();
    if (lane == 31) wsum[wid] = v;
    __syncthreads();
    if (wid == 0) {
        int w = wsum[lane];
        #pragma unroll
        for (int off = 1; off < 32; off <<= 1) {
            int n = __shfl_up_sync(0xffffffffu, w, off);
            if (lane >= off) w += n;
        }
        wsum[lane] = w;
    }
    __syncthreads();
    return v + (wid ? wsum[wid - 1] : 0);
}

// order-preserving float <-> u32
__device__ __forceinline__ unsigned fmap(float x) {
    unsigned fb = __float_as_uint(x);
    return (fb & 0x80000000u) ? ~fb : (fb | 0x80000000u);
}
__device__ __forceinline__ float funmap(unsigned mu) {
    unsigned fb = (mu & 0x80000000u) ? (mu & 0x7FFFFFFFu) : ~mu;
    return __uint_as_float(fb);
}

// descending sort order: larger key first, then smaller idx first
__device__ __forceinline__ bool kv_gt(unsigned k1, unsigned p1, unsigned k2, unsigned p2) {
    return (k1 > k2) || (k1 == k2 && p1 < p2);
}
__device__ __forceinline__ void ce_sh(unsigned* kv, unsigned* pv, int i, int j, int K) {
    unsigned k1 = kv[i], p1 = pv[i], k2 = kv[i + j], p2 = pv[i + j];
    bool sw = ((i & K) == 0) ? kv_gt(k2, p2, k1, p1) : kv_gt(k1, p1, k2, p2);
    if (sw) { kv[i] = k2; pv[i] = p2; kv[i + j] = k1; pv[i + j] = p1; }
}

// ============================ ONE fused kernel ============================
__global__ void __launch_bounds__(NT) k_fused(const float* __restrict__ logits,
                                              const float* __restrict__ temps,
                                              const int*   __restrict__ top_ks,
                                              const float* __restrict__ top_ps,
                                              const float* __restrict__ min_ps,
                                              const float* __restrict__ u,
                                              float* __restrict__ out,
                                              int V, int B, int tokens_first)
{
    const int row = blockIdx.x;
    const int tid = threadIdx.x;
    const int lane = tid & 31, wid = tid >> 5;

    // Arena layout (u32 words), 40 KB:
    //  [0..2047]     hist (phase 1) -> skv (rank keys) ; fallback fkv[0..4095]
    //  [2048..4095]  cval (candidate values)
    //  [4096..6143]  cidx (candidate indices)         ; fallback fkp[4096..8191]
    //  [6144..8191]  packed u16x2 fine bins (4096 bins in 2048 words)
    //  [8192..10239] skp (rank payloads)
    __shared__ unsigned arena[10240];
    __shared__ float wred[32];
    __shared__ int   iwsum[32];
    __shared__ float s_S, s_shift, s_mx;
    __shared__ int   s_bt, s_cnt, s_bad;
    __shared__ float sh_p0, sh_tot;

    int*      hist  = (int*)arena;
    float*    cval  = (float*)(arena + 2048);
    int*      cidx  = (int*)(arena + 4096);
    unsigned* binsw = arena + 6144;
    unsigned* skvA  = arena;
    unsigned* skpA  = arena + 8192;

    float* probs_out = tokens_first ? (out + B) : out;
    float* prow = probs_out + (size_t)row * V;
    const float* lrow = logits + (size_t)row * V;
    const float invT = 1.0f / temps[row];
    const float k2 = invT * 1.44269504f;
    const int need = V < 1024 ? V : 1024;
    const int V4 = V >> 2;
    const float4* l4 = (const float4*)lrow;

    // ---- Phase 0: zero this row's output (streaming stores drain under compute) ----
    if ((V & 3) == 0 && ((B & 3) == 0 || !tokens_first)) {
        float4* p4 = (float4*)prow;
        const float4 z4 = make_float4(0.f, 0.f, 0.f, 0.f);
        for (int i = tid; i < V4; i += NT) __stcs(p4 + i, z4);
    } else {
        for (int i = tid; i < V; i += NT) __stcs(prow + i, 0.f);
    }
    if (tid == 0) { s_cnt = 0; s_bad = 0; s_bt = 1024; }

    // ---- Phase 1: 16k-point coalesced subsample histogram -> threshold ----
    if (V > CAP) {
        for (int t = tid; t < NBINS; t += NT) hist[t] = 0;
        __syncthreads();
        int step4 = V4 / 4096; if (step4 < 1) step4 = 1;
        int ns4 = V4 / step4; if (ns4 > 4096) ns4 = 4096;
        int subN = ns4 * 4;
        for (int j = tid; j < ns4; j += NT) {
            float4 v = l4[(size_t)j * step4];
            if (v.x > 2.0f) atomicAdd(&hist[bin_of(v.x)], 1);
            if (v.y > 2.0f) atomicAdd(&hist[bin_of(v.y)], 1);
            if (v.z > 2.0f) atomicAdd(&hist[bin_of(v.z)], 1);
            if (v.w > 2.0f) atomicAdd(&hist[bin_of(v.w)], 1);
        }
        __syncthreads();
        // target expected true count ~1.55*need (>=4 sigma inside [1024, 2048])
        int tgt = (int)(((long long)need * 31LL * subN) / (20LL * (long long)V));
        if (tgt < 1) tgt = 1;
        int b = 2047 - tid;
        int v = (tid < 960) ? hist[b] : 0;
        int sfx = block_incl_scan_int(v, iwsum, lane, wid);
        if (tid < 960 && sfx >= tgt && sfx - v < tgt) s_bt = b;
        __syncthreads();
    }
    const float xthr = (V > CAP) ? ((float)s_bt * 0.03125f - 32.0f) : -FLT_MAX;
    __syncthreads();   // hist dead; s_cnt visible

    // ---- Phase 2: single full pass: max + sum(fexp) + plain-atomic gather ----
    float s = 0.f, s2 = 0.f, mx = -FLT_MAX;
    for (int i = tid; i < V4; i += NT) {
        float4 v = l4[i];
        mx = fmaxf(mx, fmaxf(fmaxf(v.x, v.y), fmaxf(v.z, v.w)));
        s  += fexp(v.x, k2) + fexp(v.y, k2);
        s2 += fexp(v.z, k2) + fexp(v.w, k2);
        #pragma unroll
        for (int c = 0; c < 4; c++) {
            float x = (c == 0) ? v.x : (c == 1) ? v.y : (c == 2) ? v.z : v.w;
            if (x >= xthr) {
                int pos = atomicAdd(&s_cnt, 1);
                if (pos < 2048) { cval[pos] = x; cidx[pos] = (i << 2) + c; }
            }
        }
    }
    s += s2;
    for (int t = (V4 << 2) + tid; t < V; t += NT) {         // tail (V%4)
        float x = lrow[t];
        mx = fmaxf(mx, x);
        s += fexp(x, k2);
        if (x >= xthr) {
            int pos = atomicAdd(&s_cnt, 1);
            if (pos < 2048) { cval[pos] = x; cidx[pos] = t; }
        }
    }

    // ---- Phase 3: reductions ----
    s = warp_red_sum(s);
    if (lane == 0) wred[wid] = s;
    __syncthreads();
    if (wid == 0) { float t = warp_red_sum(wred[lane]); if (lane == 0) s_S = t; }
    __syncthreads();
    mx = warp_red_max(mx);
    if (lane == 0) wred[wid] = mx;
    __syncthreads();
    if (wid == 0) {
        float t = warp_red_max(wred[lane]);
        if (lane == 0) {
            s_mx = t;
            float mxT = t * invT;
            s_shift = (mxT > 80.f || !isfinite(s_S)) ? mxT : 0.f;
        }
    }
    __syncthreads();
    const float shift = s_shift;
    if (shift != 0.f) {        // rare overflow-safe recompute (precise path)
        s = 0.f;
        for (int t = tid; t < V; t += NT) s += expf(lrow[t] * invT - shift);
        s = warp_red_sum(s);
        if (lane == 0) wred[wid] = s;
        __syncthreads();
        if (wid == 0) { float t = warp_red_sum(wred[lane]); if (lane == 0) s_S = t; }
        __syncthreads();
    }

    int C = s_cnt;
    const float lo = xthr, hi = s_mx;
    const float range = hi - lo;
    bool ok = (V > CAP) && (C >= need) && (C <= 2048) && (range > 0.f) && isfinite(range);

    unsigned *pk = skvA, *pp = skpA;

    if (ok) {
        // ---- Phase 4: histogram ranking (4096 fine bins, packed u16 counters) ----
        const float scale = (float)FB / range;
        unsigned k0 = 0, k1 = 0; int i0 = 0, i1 = 0, b0 = 0, b1 = 0;
        float x0 = 0.f, x1 = 0.f;
        if (tid < C)        { x0 = cval[tid];        i0 = cidx[tid];        k0 = fmap(x0); }
        if (tid + 1024 < C) { x1 = cval[tid + 1024]; i1 = cidx[tid + 1024]; k1 = fmap(x1); }
        binsw[tid] = 0; binsw[tid + 1024] = 0;
        __syncthreads();
        if (tid < C) {
            b0 = (int)((x0 - lo) * scale); b0 = b0 < 0 ? 0 : (b0 > FB - 1 ? FB - 1 : b0);
            atomicAdd(&binsw[b0 >> 1], 1u << (16 * (b0 & 1)));
        }
        if (tid + 1024 < C) {
            b1 = (int)((x1 - lo) * scale); b1 = b1 < 0 ? 0 : (b1 > FB - 1 ? FB - 1 : b1);
            atomicAdd(&binsw[b1 >> 1], 1u << (16 * (b1 & 1)));
        }
        __syncthreads();
        // suffix scan in descending-bin order
        unsigned w1 = binsw[2047 - 2 * tid];
        unsigned w0 = binsw[2046 - 2 * tid];
        int cA = (int)(w1 >> 16), cB = (int)(w1 & 0xffffu);
        int cC = (int)(w0 >> 16), cD = (int)(w0 & 0xffffu);
        int tot4 = cA + cB + cC + cD;
        int base = block_incl_scan_int(tot4, iwsum, lane, wid) - tot4;
        binsw[2047 - 2 * tid] = ((unsigned)base << 16) | (unsigned)(base + cA);
        binsw[2046 - 2 * tid] = ((unsigned)(base + cA + cB) << 16) | (unsigned)(base + cA + cB + cC);
        __syncthreads();
        // scatter to rank slots
        if (tid < C) {
            unsigned old = atomicAdd(&binsw[b0 >> 1], 1u << (16 * (b0 & 1)));
            int sl = (int)((old >> (16 * (b0 & 1))) & 0xffffu);
            pk[sl] = k0; pp[sl] = (unsigned)i0;
        }
        if (tid + 1024 < C) {
            unsigned old = atomicAdd(&binsw[b1 >> 1], 1u << (16 * (b1 & 1)));
            int sl = (int)((old >> (16 * (b1 & 1))) & 0xffffu);
            pk[sl] = k1; pp[sl] = (unsigned)i1;
        }
        __syncthreads();
        // fixup within-bin order: insertion sort on contiguous same-bin runs
        #pragma unroll
        for (int e = 0; e < 2; e++) {
            int i = tid + e * 1024;
            if (i < C) {
                int bi = (int)((funmap(pk[i]) - lo) * scale); bi = bi < 0 ? 0 : (bi > FB - 1 ? FB - 1 : bi);
                int bp = -1;
                if (i > 0) {
                    bp = (int)((funmap(pk[i - 1]) - lo) * scale); bp = bp < 0 ? 0 : (bp > FB - 1 ? FB - 1 : bp);
                }
                if (bi != bp) {                       // run start
                    int L = 1;
                    while (i + L < C && L <= 16) {
                        int bn = (int)((funmap(pk[i + L]) - lo) * scale); bn = bn < 0 ? 0 : (bn > FB - 1 ? FB - 1 : bn);
                        if (bn != bi) break;
                        L++;
                    }
                    if (L > 16) { atomicExch(&s_bad, 1); }
                    else if (L > 1) {
                        unsigned lk[16], lp[16];
                        for (int t = 0; t < L; t++) { lk[t] = pk[i + t]; lp[t] = pp[i + t]; }
                        for (int a = 1; a < L; a++) {
                            unsigned ck = lk[a], cp = lp[a];
                            int b2 = a - 1;
                            while (b2 >= 0 && !kv_gt(lk[b2], lp[b2], ck, cp)) {
                                lk[b2 + 1] = lk[b2]; lp[b2 + 1] = lp[b2]; b2--;
                            }
                            lk[b2 + 1] = ck; lp[b2 + 1] = cp;
                        }
                        for (int t = 0; t < L; t++) { pk[i + t] = lk[t]; pp[i + t] = lp[t]; }
                    }
                }
            }
        }
        __syncthreads();
        if (s_bad) ok = false;
        __syncthreads();
    }

    if (!ok) {
        // ---- FALLBACK (~never): exact coarse hist -> global gather -> bitonic 4096 ----
        if (V <= CAP) {
            for (int t = tid; t < V; t += NT) { g_cval[row * CAP + t] = lrow[t]; g_cidx[row * CAP + t] = t; }
            if (tid == 0) s_cnt = V;
        } else {
            for (int t = tid; t < NBINS; t += NT) hist[t] = 0;
            __syncthreads();
            for (int t = tid; t < V; t += NT) atomicAdd(&hist[bin_of(lrow[t])], 1);
            __syncthreads();
            if (tid == 0) {
                int acc = 0, bt2 = 0;
                for (int b = NBINS - 1; b >= 0; b--) {
                    int na = acc + hist[b];
                    if (na >= need) { bt2 = (na <= CAP) ? b : (b + 1); break; }
                    acc = na;
                }
                s_bt = bt2; s_cnt = 0;
            }
            __syncthreads();
            const int bt2 = s_bt;
            for (int t = tid; t < V; t += NT) {
                float x = lrow[t];
                if (bin_of(x) >= bt2) {
                    int pos = atomicAdd(&s_cnt, 1);
                    if (pos < CAP) { g_cval[row * CAP + pos] = x; g_cidx[row * CAP + pos] = t; }
                }
            }
        }
        __syncthreads();
        C = s_cnt < CAP ? s_cnt : CAP;
        unsigned* fkv = arena;
        unsigned* fkp = arena + 4096;
        for (int i = tid; i < CAP; i += NT) {
            unsigned key = 0u, pay = 0xFFFFFFFFu;
            if (i < C) { key = fmap(g_cval[row * CAP + i]); pay = (unsigned)g_cidx[row * CAP + i]; }
            fkv[i] = key; fkp[i] = pay;
        }
        __syncthreads();
        for (int K = 2; K <= CAP; K <<= 1) {
            int j = K >> 1;
            for (; j >= 64; j >>= 1) {
                for (int c = tid; c < (CAP >> 1); c += NT) {
                    int i = ((c & ~(j - 1)) << 1) | (c & (j - 1));
                    ce_sh(fkv, fkp, i, j, K);
                }
                __syncthreads();
            }
            for (; j >= 1; j >>= 1) {
                for (int c = tid; c < (CAP >> 1); c += NT) {
                    int i = ((c & ~(j - 1)) << 1) | (c & (j - 1));
                    ce_sh(fkv, fkp, i, j, K);
                }
                __syncwarp();
            }
            __syncthreads();
        }
        pk = fkv; pp = fkp;
    }

    // ---- Phase 5: masks (reference order) + inverse-CDF sample + scatter ----
    const float S = s_S;
    float p = 0.f;
    int   myidx = 0;
    if (tid < C) {
        p = expf(funmap(pk[tid]) * invT - shift) / S;
        myidx = (int)pp[tid];
    }
    if (tid == 0) sh_p0 = p;

    float cumincl = block_incl_scan(p, wred, lane, wid);   // pre-mask cumsum

    const int   tk  = top_ks[row];
    const float tp  = top_ps[row];
    const float thr = sh_p0 * min_ps[row];
    float q = p;
    if (tid >= tk)        q = 0.f;   // top-k
    if (cumincl - q > tp) q = 0.f;   // top-p (cumsum computed pre-mask)
    if (q < thr)          q = 0.f;   // min-p

    float cq = block_incl_scan(q, wred, lane, wid);        // post-mask CDF numerator
    if (tid == NT - 1) sh_tot = cq;
    __syncthreads();
    const float tot  = sh_tot;
    const float uval = u[row];

    int rank = __syncthreads_count((cq / tot < uval) ? 1 : 0);
    if (rank > NT - 1) rank = NT - 1;
    if (rank > V - 1) rank = V - 1;

    if (tid == 0 && tokens_first) {
        out[row] = (float)(int)pp[rank];
    }
    if (q > 0.f) {
        prow[myidx] = q / tot;   // ordered after phase-0 zero stores by barriers
    }
}

extern "C" void kernel_launch(void* const* d_in, const int* in_sizes, int n_in,
                              void* d_out, int out_size)
{
    const float* logits = (const float*)d_in[0];
    const float* temps  = (const float*)d_in[1];
    const int*   topks  = (const int*)  d_in[2];
    const float* topps  = (const float*)d_in[3];
    const float* minps  = (const float*)d_in[4];
    const float* u      = (const float*)d_in[5];

    const int B = in_sizes[1];
    const int V = in_sizes[0] / B;
    float* out = (float*)d_out;
    int tokens_first = (out_size == B + B * V) ? 1 : 0;

    k_fused<<<B, NT>>>(logits, temps, topks, topps, minps, u, out, V, B, tokens_first);
}

// round 9
// speedup vs baseline: 1.6081x; 1.5547x over previous
#include <cuda_runtime.h>
#include <math.h>
#include <stdint.h>
#include <float.h>

#define MAXB  128
#define CAP   4096
#define NBINS 2048     // coarse subsample bins
#define FB    4096     // fine ranking bins
#define NT    1024

// Global candidate staging (written phase 2/3, read phase 4)
__device__ float g_cval[MAXB * CAP];
__device__ int   g_cidx[MAXB * CAP];

__device__ __forceinline__ int bin_of(float x) {
    int b = (int)floorf((x + 32.0f) * 32.0f);   // width 1/32 over [-32, 32]
    b = b < 0 ? 0 : b;
    return b > (NBINS - 1) ? (NBINS - 1) : b;
}

__device__ __forceinline__ float warp_red_sum(float v) {
    #pragma unroll
    for (int o = 16; o; o >>= 1) v += __shfl_xor_sync(0xffffffffu, v, o);
    return v;
}
__device__ __forceinline__ float warp_red_max(float v) {
    #pragma unroll
    for (int o = 16; o; o >>= 1) v = fmaxf(v, __shfl_xor_sync(0xffffffffu, v, o));
    return v;
}

__device__ __forceinline__ float block_incl_scan(float v, float* wsum, int lane, int wid) {
    #pragma unroll
    for (int off = 1; off < 32; off <<= 1) {
        float n = __shfl_up_sync(0xffffffffu, v, off);
        if (lane >= off) v += n;
    }
    __syncthreads();
    if (lane == 31) wsum[wid] = v;
    __syncthreads();
    if (wid == 0) {
        float w = wsum[lane];
        #pragma unroll
        for (int off = 1; off < 32; off <<= 1) {
            float n = __shfl_up_sync(0xffffffffu, w, off);
            if (lane >= off) w += n;
        }
        wsum[lane] = w;
    }
    __syncthreads();
    return v + (wid ? wsum[wid - 1] : 0.f);
}

__device__ __forceinline__ int block_incl_scan_int(int v, int* wsum, int lane, int wid) {
    #pragma unroll
    for (int off = 1; off < 32; off <<= 1) {
        int n = __shfl_up_sync(0xffffffffu, v, off);
        if (lane >= off) v += n;
    }
    __syncthreads();
    if (lane == 31) wsum[wid] = v;
    __syncthreads();
    if (wid == 0) {
        int w = wsum[lane];
        #pragma unroll
        for (int off = 1; off < 32; off <<= 1) {
            int n = __shfl_up_sync(0xffffffffu, w, off);
            if (lane >= off) w += n;
        }
        wsum[lane] = w;
    }
    __syncthreads();
    return v + (wid ? wsum[wid - 1] : 0);
}

// order-preserving float <-> u32
__device__ __forceinline__ unsigned fmap(float x) {
    unsigned fb = __float_as_uint(x);
    return (fb & 0x80000000u) ? ~fb : (fb | 0x80000000u);
}
__device__ __forceinline__ float funmap(unsigned mu) {
    unsigned fb = (mu & 0x80000000u) ? (mu & 0x7FFFFFFFu) : ~mu;
    return __uint_as_float(fb);
}

// descending order: larger key first, then smaller idx first
__device__ __forceinline__ bool kv_gt(unsigned k1, unsigned p1, unsigned k2, unsigned p2) {
    return (k1 > k2) || (k1 == k2 && p1 < p2);
}
__device__ __forceinline__ void ce_sh(unsigned* kv, unsigned* pv, int i, int j, int K) {
    unsigned k1 = kv[i], p1 = pv[i], k2 = kv[i + j], p2 = pv[i + j];
    bool sw = ((i & K) == 0) ? kv_gt(k2, p2, k1, p1) : kv_gt(k1, p1, k2, p2);
    if (sw) { kv[i] = k2; pv[i] = p2; kv[i + j] = k1; pv[i + j] = p1; }
}

// ============================ ONE fused kernel ============================
__global__ void __launch_bounds__(NT) k_fused(const float* __restrict__ logits,
                                              const float* __restrict__ temps,
                                              const int*   __restrict__ top_ks,
                                              const float* __restrict__ top_ps,
                                              const float* __restrict__ min_ps,
                                              const float* __restrict__ u,
                                              float* __restrict__ out,
                                              int V, int B, int tokens_first)
{
    const int row = blockIdx.x;
    const int tid = threadIdx.x;
    const int lane = tid & 31, wid = tid >> 5;

    // 32 KB arena, phase-aliased:
    //  phase 1: hist = arena[0..2047] (int)
    //  phase 4: bins = arena[0..4095] (int), skv = arena[4096..6143], skp = arena[6144..8191]
    //  fallback bitonic: fkv = arena[0..4095], fkp = arena[4096..8191]
    __shared__ unsigned arena[8192];
    __shared__ float wred[32];
    __shared__ int   iwsum[32];
    __shared__ float s_S, s_shift, s_mx, s_lo;
    __shared__ int   s_bt, s_cnt, s_bad;
    __shared__ float sh_p0, sh_tot;

    int* hist = (int*)arena;

    float* probs_out = tokens_first ? (out + B) : out;
    float* prow = probs_out + (size_t)row * V;
    const float* lrow = logits + (size_t)row * V;
    const float invT = 1.0f / temps[row];
    const int need = V < 1024 ? V : 1024;
    const int V4 = V >> 2;
    const float4* l4 = (const float4*)lrow;

    // ---- Phase 0: zero this row's output (streaming stores drain under compute) ----
    if ((V & 3) == 0 && ((B & 3) == 0 || !tokens_first)) {
        float4* p4 = (float4*)prow;
        const float4 z4 = make_float4(0.f, 0.f, 0.f, 0.f);
        for (int i = tid; i < V4; i += NT) __stcs(p4 + i, z4);
    } else {
        for (int i = tid; i < V; i += NT) __stcs(prow + i, 0.f);
    }
    if (tid == 0) { s_cnt = 0; s_bad = 0; s_bt = 1024; }

    // ---- Phase 1: 16k-point coalesced subsample histogram -> threshold ----
    if (V > CAP) {
        for (int t = tid; t < NBINS; t += NT) hist[t] = 0;
        __syncthreads();
        int step4 = V4 / 4096; if (step4 < 1) step4 = 1;
        int ns4 = V4 / step4; if (ns4 > 4096) ns4 = 4096;
        int subN = ns4 * 4;
        for (int j = tid; j < ns4; j += NT) {
            float4 v = l4[(size_t)j * step4];
            if (v.x > 2.0f) atomicAdd(&hist[bin_of(v.x)], 1);
            if (v.y > 2.0f) atomicAdd(&hist[bin_of(v.y)], 1);
            if (v.z > 2.0f) atomicAdd(&hist[bin_of(v.z)], 1);
            if (v.w > 2.0f) atomicAdd(&hist[bin_of(v.w)], 1);
        }
        __syncthreads();
        // target expected true count ~1.55*need (>=4 sigma inside [1024, 2048])
        int tgt = (int)(((long long)need * 31LL * subN) / (20LL * (long long)V));
        if (tgt < 1) tgt = 1;
        int b = 2047 - tid;
        int v = (tid < 960) ? hist[b] : 0;
        int sfx = block_incl_scan_int(v, iwsum, lane, wid);
        if (tid < 960 && sfx >= tgt && sfx - v < tgt) s_bt = b;
        __syncthreads();
    }
    const float xthr = (V > CAP) ? ((float)s_bt * 0.03125f - 32.0f) : -FLT_MAX;
    if (tid == 0) s_lo = xthr;
    __syncthreads();

    // ---- Phase 2: 4-way unrolled full pass: max + sum(__expf) + gather -> global ----
    #define GATHER4(vv, bi)                                                              \
        { _Pragma("unroll")                                                              \
          for (int c = 0; c < 4; c++) {                                                  \
            float x = (c == 0) ? (vv).x : (c == 1) ? (vv).y : (c == 2) ? (vv).z : (vv).w;\
            if (x >= xthr) {                                                             \
                int pos = atomicAdd(&s_cnt, 1);                                          \
                if (pos < CAP) { g_cval[row * CAP + pos] = x;                            \
                                 g_cidx[row * CAP + pos] = ((bi) << 2) + c; }            \
            } } }

    float sA = 0.f, sB = 0.f, sC = 0.f, sD = 0.f, mx = -FLT_MAX;
    int i = tid;
    for (; i + 3 * NT < V4; i += 4 * NT) {
        float4 va = l4[i];
        float4 vb = l4[i + NT];
        float4 vc = l4[i + 2 * NT];
        float4 vd = l4[i + 3 * NT];
        mx = fmaxf(mx, fmaxf(fmaxf(va.x, va.y), fmaxf(va.z, va.w)));
        mx = fmaxf(mx, fmaxf(fmaxf(vb.x, vb.y), fmaxf(vb.z, vb.w)));
        mx = fmaxf(mx, fmaxf(fmaxf(vc.x, vc.y), fmaxf(vc.z, vc.w)));
        mx = fmaxf(mx, fmaxf(fmaxf(vd.x, vd.y), fmaxf(vd.z, vd.w)));
        sA += __expf(va.x * invT) + __expf(va.y * invT) + __expf(va.z * invT) + __expf(va.w * invT);
        sB += __expf(vb.x * invT) + __expf(vb.y * invT) + __expf(vb.z * invT) + __expf(vb.w * invT);
        sC += __expf(vc.x * invT) + __expf(vc.y * invT) + __expf(vc.z * invT) + __expf(vc.w * invT);
        sD += __expf(vd.x * invT) + __expf(vd.y * invT) + __expf(vd.z * invT) + __expf(vd.w * invT);
        GATHER4(va, i);
        GATHER4(vb, i + NT);
        GATHER4(vc, i + 2 * NT);
        GATHER4(vd, i + 3 * NT);
    }
    for (; i < V4; i += NT) {
        float4 v = l4[i];
        mx = fmaxf(mx, fmaxf(fmaxf(v.x, v.y), fmaxf(v.z, v.w)));
        sA += __expf(v.x * invT) + __expf(v.y * invT) + __expf(v.z * invT) + __expf(v.w * invT);
        GATHER4(v, i);
    }
    float s = (sA + sB) + (sC + sD);
    for (int t = (V4 << 2) + tid; t < V; t += NT) {       // tail (V % 4)
        float x = lrow[t];
        mx = fmaxf(mx, x);
        s += __expf(x * invT);
        if (x >= xthr) {
            int pos = atomicAdd(&s_cnt, 1);
            if (pos < CAP) { g_cval[row * CAP + pos] = x; g_cidx[row * CAP + pos] = t; }
        }
    }
    #undef GATHER4

    // ---- Phase 3: reductions + overflow guard + verify/fallback ----
    s = warp_red_sum(s);
    if (lane == 0) wred[wid] = s;
    __syncthreads();
    if (wid == 0) { float t = warp_red_sum(wred[lane]); if (lane == 0) s_S = t; }
    __syncthreads();
    mx = warp_red_max(mx);
    if (lane == 0) wred[wid] = mx;
    __syncthreads();
    if (wid == 0) {
        float t = warp_red_max(wred[lane]);
        if (lane == 0) {
            s_mx = t;
            float mxT = t * invT;
            s_shift = (mxT > 80.f || !isfinite(s_S)) ? mxT : 0.f;
        }
    }
    __syncthreads();
    const float shift = s_shift;
    if (shift != 0.f) {        // rare overflow-safe recompute (precise path)
        s = 0.f;
        for (int t = tid; t < V; t += NT) s += expf(lrow[t] * invT - shift);
        s = warp_red_sum(s);
        if (lane == 0) wred[wid] = s;
        __syncthreads();
        if (wid == 0) { float t = warp_red_sum(wred[lane]); if (lane == 0) s_S = t; }
        __syncthreads();
    }

    int C = s_cnt;
    if (V > CAP && !(C >= need && C <= CAP)) {
        // FALLBACK (~never): exact coarse histogram -> guaranteed threshold -> regather
        for (int t = tid; t < NBINS; t += NT) hist[t] = 0;
        __syncthreads();
        for (int t = tid; t < V; t += NT) atomicAdd(&hist[bin_of(lrow[t])], 1);
        __syncthreads();
        if (tid == 0) {
            int acc = 0, bt2 = 0;
            for (int b = NBINS - 1; b >= 0; b--) {
                int na = acc + hist[b];
                if (na >= need) { bt2 = (na <= CAP) ? b : (b + 1); break; }
                acc = na;
            }
            s_bt = bt2; s_cnt = 0;
            s_lo = (float)bt2 * 0.03125f - 32.0f - 0.0625f;   // safe lower bound
        }
        __syncthreads();
        const int bt2 = s_bt;
        for (int t = tid; t < V; t += NT) {
            float x = lrow[t];
            if (bin_of(x) >= bt2) {
                int pos = atomicAdd(&s_cnt, 1);
                if (pos < CAP) { g_cval[row * CAP + pos] = x; g_cidx[row * CAP + pos] = t; }
            }
        }
        __syncthreads();
        C = s_cnt;
    }
    C = C < CAP ? C : CAP;
    __syncthreads();

    // ---- Phase 4: ranking (R6 k_sample) ----
    const float lo = s_lo, hi = s_mx;
    const float range = hi - lo;
    int*      bins = (int*)arena;
    unsigned* skv  = arena + 4096;
    unsigned* skp  = arena + 6144;
    unsigned *pk = skv, *pp = skp;

    bool fast = (C <= 2048) && (range > 0.f) && isfinite(range);

    if (fast) {
        const float scale = (float)FB / range;
        unsigned k0 = 0, k1 = 0; int i0 = 0, i1 = 0, b0 = 0, b1 = 0;
        float x0 = 0.f, x1 = 0.f;
        if (tid < C)        { x0 = g_cval[row * CAP + tid];        i0 = g_cidx[row * CAP + tid];        k0 = fmap(x0); }
        if (tid + 1024 < C) { x1 = g_cval[row * CAP + tid + 1024]; i1 = g_cidx[row * CAP + tid + 1024]; k1 = fmap(x1); }
        #pragma unroll
        for (int t = 0; t < 4; t++) bins[tid + t * NT] = 0;
        __syncthreads();
        if (tid < C) {
            b0 = (int)((x0 - lo) * scale); b0 = b0 < 0 ? 0 : (b0 > FB - 1 ? FB - 1 : b0);
            atomicAdd(&bins[b0], 1);
        }
        if (tid + 1024 < C) {
            b1 = (int)((x1 - lo) * scale); b1 = b1 < 0 ? 0 : (b1 > FB - 1 ? FB - 1 : b1);
            atomicAdd(&bins[b1], 1);
        }
        __syncthreads();
        // suffix scan in descending-bin order; thread t owns bins 4095-4t..4092-4t
        int c0c = bins[4095 - 4 * tid];
        int c1c = bins[4094 - 4 * tid];
        int c2c = bins[4093 - 4 * tid];
        int c3c = bins[4092 - 4 * tid];
        int tot4 = c0c + c1c + c2c + c3c;
        int base = block_incl_scan_int(tot4, iwsum, lane, wid) - tot4;
        bins[4095 - 4 * tid] = base;
        bins[4094 - 4 * tid] = base + c0c;
        bins[4093 - 4 * tid] = base + c0c + c1c;
        bins[4092 - 4 * tid] = base + c0c + c1c + c2c;
        __syncthreads();
        if (tid < C)        { int sl = atomicAdd(&bins[b0], 1); skv[sl] = k0; skp[sl] = (unsigned)i0; }
        if (tid + 1024 < C) { int sl = atomicAdd(&bins[b1], 1); skv[sl] = k1; skp[sl] = (unsigned)i1; }
        __syncthreads();
        // fixup within-bin order: insertion sort on contiguous same-bin runs
        #pragma unroll
        for (int e = 0; e < 2; e++) {
            int ii = tid + e * 1024;
            if (ii < C) {
                int bi = (int)((funmap(skv[ii]) - lo) * scale); bi = bi < 0 ? 0 : (bi > FB - 1 ? FB - 1 : bi);
                int bp = -1;
                if (ii > 0) {
                    bp = (int)((funmap(skv[ii - 1]) - lo) * scale); bp = bp < 0 ? 0 : (bp > FB - 1 ? FB - 1 : bp);
                }
                if (bi != bp) {                       // run start
                    int L = 1;
                    while (ii + L < C && L <= 16) {
                        int bn = (int)((funmap(skv[ii + L]) - lo) * scale); bn = bn < 0 ? 0 : (bn > FB - 1 ? FB - 1 : bn);
                        if (bn != bi) break;
                        L++;
                    }
                    if (L > 16) { atomicExch(&s_bad, 1); }
                    else if (L > 1) {
                        unsigned lk[16], lp[16];
                        for (int t = 0; t < L; t++) { lk[t] = skv[ii + t]; lp[t] = skp[ii + t]; }
                        for (int a = 1; a < L; a++) {
                            unsigned ck = lk[a], cp = lp[a];
                            int b2 = a - 1;
                            while (b2 >= 0 && !kv_gt(lk[b2], lp[b2], ck, cp)) {
                                lk[b2 + 1] = lk[b2]; lp[b2 + 1] = lp[b2]; b2--;
                            }
                            lk[b2 + 1] = ck; lp[b2 + 1] = cp;
                        }
                        for (int t = 0; t < L; t++) { skv[ii + t] = lk[t]; skp[ii + t] = lp[t]; }
                    }
                }
            }
        }
        __syncthreads();
        if (s_bad) fast = false;
        __syncthreads();
    }

    if (!fast) {
        // exact bitonic on 4096 (rare)
        unsigned* fkv = arena;
        unsigned* fkp = arena + 4096;
        for (int ii = tid; ii < CAP; ii += NT) {
            unsigned key = 0u, pay = 0xFFFFFFFFu;
            if (ii < C) { key = fmap(g_cval[row * CAP + ii]); pay = (unsigned)g_cidx[row * CAP + ii]; }
            fkv[ii] = key; fkp[ii] = pay;
        }
        __syncthreads();
        for (int K = 2; K <= CAP; K <<= 1) {
            int j = K >> 1;
            for (; j >= 64; j >>= 1) {
                for (int c = tid; c < (CAP >> 1); c += NT) {
                    int ii = ((c & ~(j - 1)) << 1) | (c & (j - 1));
                    ce_sh(fkv, fkp, ii, j, K);
                }
                __syncthreads();
            }
            for (; j >= 1; j >>= 1) {
                for (int c = tid; c < (CAP >> 1); c += NT) {
                    int ii = ((c & ~(j - 1)) << 1) | (c & (j - 1));
                    ce_sh(fkv, fkp, ii, j, K);
                }
                __syncwarp();
            }
            __syncthreads();
        }
        pk = fkv; pp = fkp;
    }

    // ---- Phase 5: masks (reference order) + inverse-CDF sample + scatter ----
    const float S = s_S;
    float p = 0.f;
    int   myidx = 0;
    if (tid < C) {
        p = expf(funmap(pk[tid]) * invT - shift) / S;
        myidx = (int)pp[tid];
    }
    if (tid == 0) sh_p0 = p;

    float cumincl = block_incl_scan(p, wred, lane, wid);   // pre-mask cumsum

    const int   tk  = top_ks[row];
    const float tp  = top_ps[row];
    const float thr = sh_p0 * min_ps[row];
    float q = p;
    if (tid >= tk)        q = 0.f;   // top-k
    if (cumincl - q > tp) q = 0.f;   // top-p (cumsum computed pre-mask)
    if (q < thr)          q = 0.f;   // min-p

    float cq = block_incl_scan(q, wred, lane, wid);        // post-mask CDF numerator
    if (tid == NT - 1) sh_tot = cq;
    __syncthreads();
    const float tot  = sh_tot;
    const float uval = u[row];

    int rank = __syncthreads_count((cq / tot < uval) ? 1 : 0);
    if (rank > NT - 1) rank = NT - 1;
    if (rank > V - 1) rank = V - 1;

    if (tid == 0 && tokens_first) {
        out[row] = (float)(int)pp[rank];
    }
    if (q > 0.f) {
        prow[myidx] = q / tot;   // ordered after phase-0 zero stores by barriers
    }
}

extern "C" void kernel_launch(void* const* d_in, const int* in_sizes, int n_in,
                              void* d_out, int out_size)
{
    const float* logits = (const float*)d_in[0];
    const float* temps  = (const float*)d_in[1];
    const int*   topks  = (const int*)  d_in[2];
    const float* topps  = (const float*)d_in[3];
    const float* minps  = (const float*)d_in[4];
    const float* u      = (const float*)d_in[5];

    const int B = in_sizes[1];
    const int V = in_sizes[0] / B;
    float* out = (float*)d_out;
    int tokens_first = (out_size == B + B * V) ? 1 : 0;

    k_fused<<<B, NT>>>(logits, temps, topks, topps, minps, u, out, V, B, tokens_first);
}